// round 1
// baseline (speedup 1.0000x reference)
#include <cuda_runtime.h>

#define T_LEN 4096
#define B_SZ  2048
#define H_SZ  10

// Accurate fast tanh: tanh(s) = 1 - 2/(exp(2s)+1), via MUFU.EX2 + MUFU.RCP.
// abs err ~1e-7 — safe across the 4096-step recurrence (rel_err budget 1e-3).
__device__ __forceinline__ float fast_tanh(float s) {
    float z = s * 2.8853900817779268f;  // 2*log2(e)
    float e;
    asm("ex2.approx.ftz.f32 %0, %1;" : "=f"(e) : "f"(z));
    float d = e + 1.0f;
    float r;
    asm("rcp.approx.ftz.f32 %0, %1;" : "=f"(r) : "f"(d));
    return fmaf(-2.0f, r, 1.0f);
}

// Layout: 10 lanes per batch chain, 3 chains per warp (lanes 0-29; 30,31 idle).
// Lane (g, j) computes h_new[j] for batch b = blockIdx.x*3 + g, then a 10-wide
// shfl all-gather replicates h across the group for the next step's matvec.
__global__ void __launch_bounds__(32) rnn_kernel(
    const float* __restrict__ x,    const float* __restrict__ h0,
    const float* __restrict__ Wih,  const float* __restrict__ bih,
    const float* __restrict__ Whh,  const float* __restrict__ bhh,
    const float* __restrict__ Wout, const float* __restrict__ bout,
    float* __restrict__ out)
{
    const int lane = threadIdx.x & 31;
    const int g    = lane / 10;          // 0..2 valid, 3 for lanes 30/31
    const int j    = lane - g * 10;      // 0..9
    const int b    = blockIdx.x * 3 + g;
    const bool valid = (g < 3) && (b < B_SZ);
    const int  bc  = valid ? b : 0;      // clamped for loads

    // Per-lane weights (broadcast loads, L1-resident after first warp).
    float w[H_SZ], wo[H_SZ], h[H_SZ];
#pragma unroll
    for (int k = 0; k < H_SZ; k++) w[k] = __ldg(Whh + j * H_SZ + k);
#pragma unroll
    for (int k = 0; k < H_SZ; k++) wo[k] = __ldg(Wout + k);
    const float wih  = __ldg(Wih + j);
    const float bias = __ldg(bih + j) + __ldg(bhh + j);
    const float bo   = __ldg(bout);
#pragma unroll
    for (int k = 0; k < H_SZ; k++) h[k] = __ldg(h0 + bc * H_SZ + k);

    const int base = (g < 3 ? g : 0) * 10;   // shfl group base lane
    const unsigned mask = 0xffffffffu;

    // Software prefetch ring for x (stride B between steps — L1-miss every step
    // otherwise, and ~1 warp/SMSP cannot hide L2 latency).
    float xbuf[8];
#pragma unroll
    for (int i = 0; i < 8; i++) xbuf[i] = __ldg(x + i * B_SZ + bc);

    for (int t0 = 0; t0 < T_LEN; t0 += 8) {
#pragma unroll
        for (int u = 0; u < 8; u++) {
            const int t = t0 + u;
            const float xv = xbuf[u];
            int tp = t + 8; if (tp > T_LEN - 1) tp = T_LEN - 1;
            xbuf[u] = __ldg(x + tp * B_SZ + bc);

            // s = x*Wih[j] + b[j] + W_hh[j,:] . h   (two FMA chains for ILP)
            float acc0 = fmaf(xv, wih, bias);
            float acc1 = w[1] * h[1];
            acc0 = fmaf(w[0], h[0], acc0);
            acc1 = fmaf(w[3], h[3], acc1);
            acc0 = fmaf(w[2], h[2], acc0);
            acc1 = fmaf(w[5], h[5], acc1);
            acc0 = fmaf(w[4], h[4], acc0);
            acc1 = fmaf(w[7], h[7], acc1);
            acc0 = fmaf(w[6], h[6], acc0);
            acc1 = fmaf(w[9], h[9], acc1);
            acc0 = fmaf(w[8], h[8], acc0);
            const float s = acc0 + acc1;

            const float hn = fast_tanh(s);

            // All-gather h_new across the 10-lane group (independent shuffles).
#pragma unroll
            for (int k = 0; k < H_SZ; k++)
                h[k] = __shfl_sync(mask, hn, base + k);

            // y = Wout . h + b_out (issued once per warp; lane j==0 stores)
            float y0 = fmaf(wo[0], h[0], bo);
            float y1 = wo[1] * h[1];
            y0 = fmaf(wo[2], h[2], y0);
            y1 = fmaf(wo[3], h[3], y1);
            y0 = fmaf(wo[4], h[4], y0);
            y1 = fmaf(wo[5], h[5], y1);
            y0 = fmaf(wo[6], h[6], y0);
            y1 = fmaf(wo[7], h[7], y1);
            y0 = fmaf(wo[8], h[8], y0);
            y1 = fmaf(wo[9], h[9], y1);
            if (j == 0 && valid) out[t * B_SZ + b] = y0 + y1;
        }
    }

    // h_last: [1, B, H] appended after out [T, B, 1]
    if (valid) out[T_LEN * B_SZ + b * H_SZ + j] = h[j];
}

extern "C" void kernel_launch(void* const* d_in, const int* in_sizes, int n_in,
                              void* d_out, int out_size) {
    (void)in_sizes; (void)n_in; (void)out_size;
    const float* x    = (const float*)d_in[0];
    const float* h0   = (const float*)d_in[1];
    const float* Wih  = (const float*)d_in[2];
    const float* bih  = (const float*)d_in[3];
    const float* Whh  = (const float*)d_in[4];
    const float* bhh  = (const float*)d_in[5];
    const float* Wout = (const float*)d_in[6];
    const float* bout = (const float*)d_in[7];

    // 683 warps = ceil(2048/3) batch groups of 3 chains each.
    rnn_kernel<<<683, 32>>>(x, h0, Wih, bih, Whh, bhh, Wout, bout, (float*)d_out);
}

// round 2
// speedup vs baseline: 1.0146x; 1.0146x over previous
#include <cuda_runtime.h>

#define T_LEN 4096
#define B_SZ  2048
#define H_SZ  10

// Layout: 16 lanes per batch chain, 2 chains per warp -> 1024 warps (W=1.73/SMSP).
// Distributed h: lane j (0..9) holds only h[j]. Shuffles distribute h at the TOP
// of each step and feed the FMA dot chain directly (shfl latency overlaps the dot
// instead of trailing the tanh). Lane j==10 is the output lane: its "weight row"
// is W_out and its "bias" is b_out, so the SAME fma instructions compute
// y = W_out . h + b_out at zero extra issue cost. Since y_t needs h_{t+1}, the
// output lane's value at iteration t is out[t-1] (stored shifted; epilogue does
// the last one). tanh input scale 2*log2(e) is folded into the weights.
__global__ void __launch_bounds__(128) rnn_kernel(
    const float* __restrict__ x,    const float* __restrict__ h0,
    const float* __restrict__ Wih,  const float* __restrict__ bih,
    const float* __restrict__ Whh,  const float* __restrict__ bhh,
    const float* __restrict__ Wout, const float* __restrict__ bout,
    float* __restrict__ out)
{
    const int tid  = threadIdx.x;
    const int lane = tid & 31;
    const int sub  = lane >> 4;        // which chain within the warp (0/1)
    const int j    = lane & 15;        // role within the 16-lane group
    const int warp_global = blockIdx.x * (blockDim.x >> 5) + (tid >> 5);
    const int b    = warp_global * 2 + sub;      // batch chain, 0..2047
    const float c  = 2.8853900817779268f;        // 2*log2(e)

    float w[H_SZ], wih_s, bias_s, hn;
    if (j < H_SZ) {
        // recurrence lane: row j of W_hh, scaled by c (folds tanh input scale)
#pragma unroll
        for (int k = 0; k < H_SZ; k++) w[k] = c * __ldg(Whh + j * H_SZ + k);
        wih_s  = c * __ldg(Wih + j);
        bias_s = c * (__ldg(bih + j) + __ldg(bhh + j));
        hn     = __ldg(h0 + b * H_SZ + j);
    } else {
        // output lane(s): row = W_out, bias = b_out, no x term
#pragma unroll
        for (int k = 0; k < H_SZ; k++) w[k] = __ldg(Wout + k);
        wih_s  = 0.0f;
        bias_s = __ldg(bout);
        hn     = 0.0f;
    }

    const unsigned mask = 0xffffffffu;

    // Software prefetch ring for x (stride B between steps).
    float xbuf[8];
#pragma unroll
    for (int i = 0; i < 8; i++) xbuf[i] = __ldg(x + i * B_SZ + b);

    for (int t0 = 0; t0 < T_LEN; t0 += 8) {
#pragma unroll
        for (int u = 0; u < 8; u++) {
            const int t = t0 + u;
            const float xv = xbuf[u];
            int tp = t + 8; if (tp > T_LEN - 1) tp = T_LEN - 1;
            xbuf[u] = __ldg(x + tp * B_SZ + b);

            // Distribute h_t and run the dot as shuffles arrive.
            float acc = fmaf(xv, wih_s, bias_s);
#pragma unroll
            for (int k = 0; k < H_SZ; k++) {
                const float hv = __shfl_sync(mask, hn, k, 16);
                acc = fmaf(w[k], hv, acc);
            }

            // Output lane: acc = W_out . h_t + b_out = out[t-1].
            if (j == H_SZ && t > 0) out[(t - 1) * B_SZ + b] = acc;

            // h_{t+1} = tanh_scaled(acc): tanh(s) = 1 - 2/(exp2(c*s')+1),
            // scale already folded into acc.
            float e;
            asm("ex2.approx.ftz.f32 %0, %1;" : "=f"(e) : "f"(acc));
            float d = e + 1.0f;
            float r;
            asm("rcp.approx.ftz.f32 %0, %1;" : "=f"(r) : "f"(d));
            hn = fmaf(-2.0f, r, 1.0f);   // harmless garbage on output lanes
        }
    }

    // Epilogue: one more distribute of h_T for out[T-1], and store h_last.
    {
        float acc = bias_s;
#pragma unroll
        for (int k = 0; k < H_SZ; k++) {
            const float hv = __shfl_sync(mask, hn, k, 16);
            acc = fmaf(w[k], hv, acc);
        }
        if (j == H_SZ) out[(T_LEN - 1) * B_SZ + b] = acc;
        if (j <  H_SZ) out[T_LEN * B_SZ + b * H_SZ + j] = hn;  // h_last [1,B,H]
    }
}

extern "C" void kernel_launch(void* const* d_in, const int* in_sizes, int n_in,
                              void* d_out, int out_size) {
    (void)in_sizes; (void)n_in; (void)out_size;
    const float* x    = (const float*)d_in[0];
    const float* h0   = (const float*)d_in[1];
    const float* Wih  = (const float*)d_in[2];
    const float* bih  = (const float*)d_in[3];
    const float* Whh  = (const float*)d_in[4];
    const float* bhh  = (const float*)d_in[5];
    const float* Wout = (const float*)d_in[6];
    const float* bout = (const float*)d_in[7];

    // 1024 warps = 2048 chains at 2 chains/warp; 256 blocks x 128 threads.
    rnn_kernel<<<256, 128>>>(x, h0, Wih, bih, Whh, bhh, Wout, bout, (float*)d_out);
}

// round 3
// speedup vs baseline: 1.4197x; 1.3993x over previous
#include <cuda_runtime.h>

#define T_LEN 4096
#define B_SZ  2048
#define H_SZ  10

// One batch chain per warp (2048 warps, ~3.46/SMSP for latency hiding).
// Lane j<10 computes recurrence row j; lane j==10 computes the output dot for
// free (its "row" is W_out). Lanes exchange via double-buffered SMEM
// (1 STS + 3 broadcast LDS per step) instead of 10 SHFLs.
//
// "rcp-form" recurrence: communicate r = rcp(exp2(c*s)+1) (c = 2*log2 e), since
// h = 1 - 2r. The affine 1-2r is folded into consumer weights:
//   s_j = c*(Wih_j x + b_j + sum_k W_jk h_k)
//       = wih2_j * x + bias2_j + sum_k w2_jk * r_k
// with w2 = -2c*W_hh, bias2 = c*(b + rowsum(W_hh)), wih2 = c*Wih.
// Output lane: w2 = -2*W_out, bias2 = b_out + sum(W_out).
__global__ void __launch_bounds__(32) rnn_kernel(
    const float* __restrict__ x,    const float* __restrict__ h0,
    const float* __restrict__ Wih,  const float* __restrict__ bih,
    const float* __restrict__ Whh,  const float* __restrict__ bhh,
    const float* __restrict__ Wout, const float* __restrict__ bout,
    float* __restrict__ out)
{
    __shared__ float hsh[2][16];

    const int j = threadIdx.x;      // 0..31; roles: 0-9 rows, 10 output, rest idle
    const int b = blockIdx.x;       // one chain per block/warp
    const float c = 2.8853900817779268f;  // 2*log2(e)

    float w2[H_SZ], wih2 = 0.0f, bias2 = 0.0f;
    if (j < H_SZ) {
        float rs = 0.0f;
#pragma unroll
        for (int k = 0; k < H_SZ; k++) {
            float wv = __ldg(Whh + j * H_SZ + k);
            w2[k] = -2.0f * c * wv;
            rs += wv;
        }
        wih2  = c * __ldg(Wih + j);
        bias2 = c * (__ldg(bih + j) + __ldg(bhh + j) + rs);
    } else if (j == H_SZ) {
        float rs = 0.0f;
#pragma unroll
        for (int k = 0; k < H_SZ; k++) {
            float wv = __ldg(Wout + k);
            w2[k] = -2.0f * wv;
            rs += wv;
        }
        bias2 = __ldg(bout) + rs;
    } else {
#pragma unroll
        for (int k = 0; k < H_SZ; k++) w2[k] = 0.0f;
    }

    // Seed buffer 0 with r0 = (1 - h0)/2.
    if (j < H_SZ) hsh[0][j] = fmaf(-0.5f, __ldg(h0 + b * H_SZ + j), 0.5f);
    __syncwarp();

    // x prefetch ring (x is warp-uniform: all lanes load the same address).
    float xbuf[8];
#pragma unroll
    for (int i = 0; i < 8; i++) xbuf[i] = __ldg(x + i * B_SZ + b);

    float r = 0.5f;  // lane's own r value (valid for j<10 after first step)

#define RNN_STEP(T_VAL, U, PREFETCH)                                          \
    {                                                                         \
        const int t = (T_VAL);                                                \
        const float xv = xbuf[U];                                             \
        if (PREFETCH) xbuf[U] = __ldg(x + (t + 8) * B_SZ + b);                \
        const float4 ra = *(const float4*)&hsh[(U) & 1][0];                   \
        const float4 rb = *(const float4*)&hsh[(U) & 1][4];                   \
        const float2 rc = *(const float2*)&hsh[(U) & 1][8];                   \
        float a0 = fmaf(xv, wih2, bias2);                                     \
        float a1 = w2[1] * ra.y;                                              \
        a0 = fmaf(w2[0], ra.x, a0);  a1 = fmaf(w2[3], ra.w, a1);              \
        a0 = fmaf(w2[2], ra.z, a0);  a1 = fmaf(w2[5], rb.y, a1);              \
        a0 = fmaf(w2[4], rb.x, a0);  a1 = fmaf(w2[7], rb.w, a1);              \
        a0 = fmaf(w2[6], rb.z, a0);  a1 = fmaf(w2[9], rc.y, a1);              \
        a0 = fmaf(w2[8], rc.x, a0);                                           \
        const float acc = a0 + a1;                                            \
        if (j == H_SZ && t > 0) out[(t - 1) * B_SZ + b] = acc;                \
        float e;                                                              \
        asm("ex2.approx.ftz.f32 %0, %1;" : "=f"(e) : "f"(acc));               \
        const float d = e + 1.0f;                                             \
        asm("rcp.approx.ftz.f32 %0, %1;" : "=f"(r) : "f"(d));                 \
        if (j < H_SZ) hsh[((U) + 1) & 1][j] = r;                              \
        __syncwarp();                                                         \
    }

    // Main loop: t = 0 .. T-9 with prefetch (511 x 8 steps).
    for (int t0 = 0; t0 < T_LEN - 8; t0 += 8) {
        RNN_STEP(t0 + 0, 0, true)
        RNN_STEP(t0 + 1, 1, true)
        RNN_STEP(t0 + 2, 2, true)
        RNN_STEP(t0 + 3, 3, true)
        RNN_STEP(t0 + 4, 4, true)
        RNN_STEP(t0 + 5, 5, true)
        RNN_STEP(t0 + 6, 6, true)
        RNN_STEP(t0 + 7, 7, true)
    }
    // Tail: last 8 steps, no prefetch.
    {
        const int t0 = T_LEN - 8;
        RNN_STEP(t0 + 0, 0, false)
        RNN_STEP(t0 + 1, 1, false)
        RNN_STEP(t0 + 2, 2, false)
        RNN_STEP(t0 + 3, 3, false)
        RNN_STEP(t0 + 4, 4, false)
        RNN_STEP(t0 + 5, 5, false)
        RNN_STEP(t0 + 6, 6, false)
        RNN_STEP(t0 + 7, 7, false)
    }
#undef RNN_STEP

    // Epilogue. After the last step (u=7), buffer 0 holds r of h_T.
    {
        const float4 ra = *(const float4*)&hsh[0][0];
        const float4 rb = *(const float4*)&hsh[0][4];
        const float2 rc = *(const float2*)&hsh[0][8];
        float a0 = bias2;
        float a1 = w2[1] * ra.y;
        a0 = fmaf(w2[0], ra.x, a0);  a1 = fmaf(w2[3], ra.w, a1);
        a0 = fmaf(w2[2], ra.z, a0);  a1 = fmaf(w2[5], rb.y, a1);
        a0 = fmaf(w2[4], rb.x, a0);  a1 = fmaf(w2[7], rb.w, a1);
        a0 = fmaf(w2[6], rb.z, a0);  a1 = fmaf(w2[9], rc.y, a1);
        a0 = fmaf(w2[8], rc.x, a0);
        if (j == H_SZ) out[(T_LEN - 1) * B_SZ + b] = a0 + a1;
        // h_last [1,B,H]: lane j<10 holds its own r of h_T in register.
        if (j < H_SZ) out[T_LEN * B_SZ + b * H_SZ + j] = fmaf(-2.0f, r, 1.0f);
    }
}

extern "C" void kernel_launch(void* const* d_in, const int* in_sizes, int n_in,
                              void* d_out, int out_size) {
    (void)in_sizes; (void)n_in; (void)out_size;
    const float* x    = (const float*)d_in[0];
    const float* h0   = (const float*)d_in[1];
    const float* Wih  = (const float*)d_in[2];
    const float* bih  = (const float*)d_in[3];
    const float* Whh  = (const float*)d_in[4];
    const float* bhh  = (const float*)d_in[5];
    const float* Wout = (const float*)d_in[6];
    const float* bout = (const float*)d_in[7];

    // 2048 single-warp blocks: one chain per warp, ~13.8 blocks/SM.
    rnn_kernel<<<B_SZ, 32>>>(x, h0, Wih, bih, Whh, bhh, Wout, bout, (float*)d_out);
}

// round 4
// speedup vs baseline: 1.4292x; 1.0067x over previous
#include <cuda_runtime.h>

#define T_LEN 4096
#define B_SZ  2048
#define H_SZ  10

typedef unsigned long long u64;

// Packed f32x2 FMA (sm_103a): d = a*b + c elementwise on 2 packed floats.
#define FMA2(acc, w, r) \
    asm("fma.rn.f32x2 %0, %1, %2, %3;" : "=l"(acc) : "l"(w), "l"(r), "l"(acc))

__device__ __forceinline__ u64 packf2(float lo, float hi) {
    u64 v; asm("mov.b64 %0, {%1, %2};" : "=l"(v) : "f"(lo), "f"(hi)); return v;
}
__device__ __forceinline__ float2 unpackf2(u64 v) {
    float2 f; asm("mov.b64 {%0, %1}, %2;" : "=f"(f.x), "=f"(f.y) : "l"(v)); return f;
}

// One chain per warp (2048 warps). Lane j<10: recurrence row j. Lane j==10:
// output dot rides the same instructions (row = W_out). Exchange via
// double-buffered smem. rcp-form recurrence (R3): communicate
// r = rcp(exp2(c*s)+1); h = 1-2r folded into consumer weights:
//   w2 = -2c*W_hh, bias2 = c*(b + rowsum(W_hh)), wih2 = c*Wih
//   output lane: w2 = -2*W_out, bias2 = b_out + sum(W_out)
// The 10-dot runs as 5 chained fma.rn.f32x2; r-pairs come pre-packed from
// LDS.128/LDS.64 (ulonglong2 view) with zero pack instructions.
__global__ void __launch_bounds__(32) rnn_kernel(
    const float* __restrict__ x,    const float* __restrict__ h0,
    const float* __restrict__ Wih,  const float* __restrict__ bih,
    const float* __restrict__ Whh,  const float* __restrict__ bhh,
    const float* __restrict__ Wout, const float* __restrict__ bout,
    float* __restrict__ out)
{
    __shared__ __align__(16) float hsh[2][16];

    const int j = threadIdx.x;      // 0..31; roles: 0-9 rows, 10 output
    const int b = blockIdx.x;       // one chain per block/warp
    const float c = 2.8853900817779268f;  // 2*log2(e)

    float wtmp[H_SZ], wih2 = 0.0f, bias2 = 0.0f;
    if (j < H_SZ) {
        float rs = 0.0f;
#pragma unroll
        for (int k = 0; k < H_SZ; k++) {
            float wv = __ldg(Whh + j * H_SZ + k);
            wtmp[k] = -2.0f * c * wv;
            rs += wv;
        }
        wih2  = c * __ldg(Wih + j);
        bias2 = c * (__ldg(bih + j) + __ldg(bhh + j) + rs);
    } else if (j == H_SZ) {
        float rs = 0.0f;
#pragma unroll
        for (int k = 0; k < H_SZ; k++) {
            float wv = __ldg(Wout + k);
            wtmp[k] = -2.0f * wv;
            rs += wv;
        }
        bias2 = __ldg(bout) + rs;
    } else {
#pragma unroll
        for (int k = 0; k < H_SZ; k++) wtmp[k] = 0.0f;
    }
    const u64 W01 = packf2(wtmp[0], wtmp[1]);
    const u64 W23 = packf2(wtmp[2], wtmp[3]);
    const u64 W45 = packf2(wtmp[4], wtmp[5]);
    const u64 W67 = packf2(wtmp[6], wtmp[7]);
    const u64 W89 = packf2(wtmp[8], wtmp[9]);

    // Seed buffer 0 with r0 = (1 - h0)/2.
    if (j < H_SZ) hsh[0][j] = fmaf(-0.5f, __ldg(h0 + b * H_SZ + j), 0.5f);
    __syncwarp();

    // x prefetch ring (x is warp-uniform: broadcast load).
    float xbuf[8];
#pragma unroll
    for (int i = 0; i < 8; i++) xbuf[i] = __ldg(x + i * B_SZ + b);

    float r = 0.5f;  // lane's own r (valid for j<10 after first step)

#define RNN_STEP(T_VAL, U, PREFETCH)                                          \
    {                                                                         \
        const int t = (T_VAL);                                                \
        const float xv = xbuf[U];                                             \
        if (PREFETCH) xbuf[U] = __ldg(x + (t + 8) * B_SZ + b);                \
        const ulonglong2 q0 = *(const ulonglong2*)&hsh[(U) & 1][0];           \
        const ulonglong2 q1 = *(const ulonglong2*)&hsh[(U) & 1][4];           \
        const u64        q2 = *(const u64*)&hsh[(U) & 1][8];                  \
        u64 acc = packf2(fmaf(xv, wih2, bias2), 0.0f);                        \
        FMA2(acc, W01, q0.x);                                                 \
        FMA2(acc, W23, q0.y);                                                 \
        FMA2(acc, W45, q1.x);                                                 \
        FMA2(acc, W67, q1.y);                                                 \
        FMA2(acc, W89, q2);                                                   \
        const float2 ah = unpackf2(acc);                                      \
        const float s = ah.x + ah.y;                                          \
        if (j == H_SZ && t > 0) out[(t - 1) * B_SZ + b] = s;                  \
        float e;                                                              \
        asm("ex2.approx.ftz.f32 %0, %1;" : "=f"(e) : "f"(s));                 \
        const float d = e + 1.0f;                                             \
        asm("rcp.approx.ftz.f32 %0, %1;" : "=f"(r) : "f"(d));                 \
        if (j < H_SZ) hsh[((U) + 1) & 1][j] = r;                              \
        __syncwarp();                                                         \
    }

    for (int t0 = 0; t0 < T_LEN - 8; t0 += 8) {
        RNN_STEP(t0 + 0, 0, true)
        RNN_STEP(t0 + 1, 1, true)
        RNN_STEP(t0 + 2, 2, true)
        RNN_STEP(t0 + 3, 3, true)
        RNN_STEP(t0 + 4, 4, true)
        RNN_STEP(t0 + 5, 5, true)
        RNN_STEP(t0 + 6, 6, true)
        RNN_STEP(t0 + 7, 7, true)
    }
    {
        const int t0 = T_LEN - 8;
        RNN_STEP(t0 + 0, 0, false)
        RNN_STEP(t0 + 1, 1, false)
        RNN_STEP(t0 + 2, 2, false)
        RNN_STEP(t0 + 3, 3, false)
        RNN_STEP(t0 + 4, 4, false)
        RNN_STEP(t0 + 5, 5, false)
        RNN_STEP(t0 + 6, 6, false)
        RNN_STEP(t0 + 7, 7, false)
    }
#undef RNN_STEP

    // Epilogue: buffer 0 holds r(h_T). out[T-1] = W_out.h_T + b_out; h_last.
    {
        const ulonglong2 q0 = *(const ulonglong2*)&hsh[0][0];
        const ulonglong2 q1 = *(const ulonglong2*)&hsh[0][4];
        const u64        q2 = *(const u64*)&hsh[0][8];
        u64 acc = packf2(bias2, 0.0f);
        FMA2(acc, W01, q0.x);
        FMA2(acc, W23, q0.y);
        FMA2(acc, W45, q1.x);
        FMA2(acc, W67, q1.y);
        FMA2(acc, W89, q2);
        const float2 ah = unpackf2(acc);
        if (j == H_SZ) out[(T_LEN - 1) * B_SZ + b] = ah.x + ah.y;
        if (j <  H_SZ) out[T_LEN * B_SZ + b * H_SZ + j] = fmaf(-2.0f, r, 1.0f);
    }
}

extern "C" void kernel_launch(void* const* d_in, const int* in_sizes, int n_in,
                              void* d_out, int out_size) {
    (void)in_sizes; (void)n_in; (void)out_size;
    const float* x    = (const float*)d_in[0];
    const float* h0   = (const float*)d_in[1];
    const float* Wih  = (const float*)d_in[2];
    const float* bih  = (const float*)d_in[3];
    const float* Whh  = (const float*)d_in[4];
    const float* bhh  = (const float*)d_in[5];
    const float* Wout = (const float*)d_in[6];
    const float* bout = (const float*)d_in[7];

    rnn_kernel<<<B_SZ, 32>>>(x, h0, Wih, bih, Whh, bhh, Wout, bout, (float*)d_out);
}